// round 13
// baseline (speedup 1.0000x reference)
#include <cuda_runtime.h>
#include <cstdint>

typedef unsigned long long ull;
typedef unsigned int u32;

#define L 512
#define H 1024
#define C 2

// Scratch: split-K partials (k-half 0 and 1)
__device__ float g_ap0[L * H];
__device__ float g_ap1[L * H];
__device__ float g_bp0[L * H];
__device__ float g_bp1[L * H];
__device__ float g_f[L * L * C];   // unsymmetrized logits f[i][j][c]

// ---- packed f32x2 helpers ----
__device__ __forceinline__ ull ffma2(ull a, ull b, ull c) {
    ull d;
    asm("fma.rn.f32x2 %0, %1, %2, %3;" : "=l"(d) : "l"(a), "l"(b), "l"(c));
    return d;
}
__device__ __forceinline__ ull fadd2(ull a, ull b) {
    ull d;
    asm("add.rn.f32x2 %0, %1, %2;" : "=l"(d) : "l"(a), "l"(b));
    return d;
}
__device__ __forceinline__ float2 u2f2(ull u) {
    float2 v;
    asm("mov.b64 {%0, %1}, %2;" : "=f"(v.x), "=f"(v.y) : "l"(u));
    return v;
}
__device__ __forceinline__ ull tanh2(ull x) {
    ull r;
    asm("{\n\t"
        ".reg .f32 lo, hi;\n\t"
        "mov.b64 {lo, hi}, %1;\n\t"
        "tanh.approx.f32 lo, lo;\n\t"
        "tanh.approx.f32 hi, hi;\n\t"
        "mov.b64 %0, {lo, hi};\n\t"
        "}" : "=l"(r) : "l"(x));
    return r;
}
__device__ __forceinline__ u32 smem_u32(const void* p) {
    u32 a;
    asm("{ .reg .u64 tmp; cvta.to.shared.u64 tmp, %1; cvt.u32.u64 %0, tmp; }"
        : "=r"(a) : "l"(p));
    return a;
}
__device__ __forceinline__ void mma_tf32(float c[4], u32 a0, u32 a1, u32 a2, u32 a3,
                                         u32 b0, u32 b1) {
    asm("mma.sync.aligned.m16n8k8.row.col.f32.tf32.tf32.f32 "
        "{%0,%1,%2,%3}, {%4,%5,%6,%7}, {%8,%9}, {%0,%1,%2,%3};"
        : "+f"(c[0]), "+f"(c[1]), "+f"(c[2]), "+f"(c[3])
        : "r"(a0), "r"(a1), "r"(a2), "r"(a3), "r"(b0), "r"(b1));
}
__device__ __forceinline__ void ldsm_x4(u32& r0, u32& r1, u32& r2, u32& r3, u32 addr) {
    asm volatile("ldmatrix.sync.aligned.m8n8.x4.shared.b16 {%0,%1,%2,%3}, [%4];"
                 : "=r"(r0), "=r"(r1), "=r"(r2), "=r"(r3) : "r"(addr));
}
__device__ __forceinline__ void cp16(u32 dst, const void* src) {
    asm volatile("cp.async.ca.shared.global [%0], [%1], 16;"
                 :: "r"(dst), "l"(src) : "memory");
}
#define CP_COMMIT() asm volatile("cp.async.commit_group;" ::: "memory")
#define CP_WAIT1()  asm volatile("cp.async.wait_group 1;" ::: "memory")

// ============================================================
// Kernel 1: tf32 MMA GEMM, split-K=2. CTA 128 thr, tile
// 64l x 32o x 512k, both ap/bp. Grid (32,8,2) = 512 CTAs.
// cp.async 3-stage, ldmatrix, raw-f32-as-tf32 (R10 mainloop).
// ============================================================
#define B_PAD 36
#define S_WORDS (128 * B_PAD)        // A(64 rows) + WA(32) + WB(32)
#define K1_SMEM (3 * S_WORDS * 4)    // 55296 bytes
#define KHALF 512
#define NCH (KHALF / 32)             // 16 chunks

__global__ __launch_bounds__(128) void k1_mma(const float* __restrict__ x,
                                              const float* __restrict__ W1,
                                              const float* __restrict__ b1) {
    extern __shared__ float sm[];
    const u32 smb = smem_u32(sm);

    const int t = threadIdx.x;
    const int lane = t & 31;
    const int wid = t >> 5;
    const int gid = lane >> 2;
    const int tig = lane & 3;
    const int wm = wid & 1;           // 2 m-warps (32 rows each)
    const int wn = wid >> 1;          // 2 n-warps (16 cols each)
    const int oblk = blockIdx.x * 32;
    const int lblk = blockIdx.y * 64;
    const int kz = blockIdx.z;        // k-half

    // loader: base row r (0..15), 16B chunk c4
    const int r = t >> 3;
    const int c4 = (t & 7) * 4;
    const float* xg = x + (lblk + r) * H + kz * KHALF + c4;
    const float* wg = W1 + (oblk + r) * (2 * H) + kz * KHALF + c4;

    // ldmatrix per-lane offsets (word units within a stage)
    const int q = lane >> 3, l7 = lane & 7;
    const u32 a_off = (u32)((wm * 32 + ((q & 1) << 3) + l7) * B_PAD + ((q >> 1) << 2));
    const u32 b_off = (u32)((64 + (q >> 1) * 32 + wn * 16 + l7) * B_PAD + ((q & 1) << 2));

    float accA[2][2][4], accB[2][2][4];
#pragma unroll
    for (int mi = 0; mi < 2; mi++)
#pragma unroll
        for (int na = 0; na < 2; na++)
#pragma unroll
            for (int k = 0; k < 4; k++) { accA[mi][na][k] = 0.f; accB[mi][na][k] = 0.f; }

#define PREFETCH(chunk)                                                     \
    do {                                                                    \
        const int kb = (chunk) * 32;                                        \
        const u32 sb = smb + ((chunk) % 3) * S_WORDS * 4;                   \
        _Pragma("unroll")                                                   \
        for (int qq = 0; qq < 4; qq++)                                      \
            cp16(sb + ((r + 16 * qq) * B_PAD + c4) * 4,                     \
                 xg + 16 * qq * H + kb);                                    \
        _Pragma("unroll")                                                   \
        for (int qq = 0; qq < 2; qq++) {                                    \
            cp16(sb + ((64 + r + 16 * qq) * B_PAD + c4) * 4,                \
                 wg + 16 * qq * (2 * H) + kb);                              \
            cp16(sb + ((96 + r + 16 * qq) * B_PAD + c4) * 4,                \
                 wg + 16 * qq * (2 * H) + kb + H);                          \
        }                                                                   \
    } while (0)

#define COMPUTE(stg)                                                        \
    do {                                                                    \
        const u32 abase = smb + (stg) * S_WORDS * 4 + a_off * 4;            \
        const u32 bbase = smb + (stg) * S_WORDS * 4 + b_off * 4;            \
        _Pragma("unroll")                                                   \
        for (int ks = 0; ks < 4; ks++) {                                    \
            u32 A[2][4];                                                    \
            _Pragma("unroll")                                               \
            for (int mi = 0; mi < 2; mi++)                                  \
                ldsm_x4(A[mi][0], A[mi][1], A[mi][2], A[mi][3],             \
                        abase + (mi * 16 * B_PAD + ks * 8) * 4);            \
            _Pragma("unroll")                                               \
            for (int na = 0; na < 2; na++) {                                \
                u32 B0, B1, B2, B3;                                         \
                ldsm_x4(B0, B1, B2, B3,                                     \
                        bbase + (na * 8 * B_PAD + ks * 8) * 4);             \
                _Pragma("unroll")                                           \
                for (int mi = 0; mi < 2; mi++) {                            \
                    mma_tf32(accA[mi][na], A[mi][0], A[mi][1], A[mi][2],    \
                             A[mi][3], B0, B1);                             \
                    mma_tf32(accB[mi][na], A[mi][0], A[mi][1], A[mi][2],    \
                             A[mi][3], B2, B3);                             \
                }                                                           \
            }                                                               \
        }                                                                   \
    } while (0)

    PREFETCH(0); CP_COMMIT();
    PREFETCH(1); CP_COMMIT();

#pragma unroll 1
    for (int it = 0; it < NCH; it++) {
        CP_WAIT1();
        __syncthreads();
        if (it + 2 < NCH) PREFETCH(it + 2);
        CP_COMMIT();
        COMPUTE(it % 3);
    }

    // epilogue: b1 folded into k-half 0 only.
    float* apd = kz ? g_ap1 : g_ap0;
    float* bpd = kz ? g_bp1 : g_bp0;
#pragma unroll
    for (int mi = 0; mi < 2; mi++) {
        const int row0 = lblk + wm * 32 + mi * 16 + gid;
#pragma unroll
        for (int na = 0; na < 2; na++) {
            const int col = oblk + wn * 16 + na * 8 + tig * 2;
            float2 bv = make_float2(0.f, 0.f);
            if (kz == 0) bv = *(const float2*)&b1[col];
            float2 v;
            v.x = accA[mi][na][0] + bv.x; v.y = accA[mi][na][1] + bv.y;
            *(float2*)&apd[row0 * H + col] = v;
            v.x = accA[mi][na][2] + bv.x; v.y = accA[mi][na][3] + bv.y;
            *(float2*)&apd[(row0 + 8) * H + col] = v;
            v.x = accB[mi][na][0]; v.y = accB[mi][na][1];
            *(float2*)&bpd[row0 * H + col] = v;
            v.x = accB[mi][na][2]; v.y = accB[mi][na][3];
            *(float2*)&bpd[(row0 + 8) * H + col] = v;
        }
    }
#undef PREFETCH
#undef COMPUTE
}

// ============================================================
// Kernel 2: f[i,j,c] = sum_h tanh(ap[j,h] + bp[i,h]) * W2[c,h]
// Tile 16i x 32j, 256 threads, HC=64. MUFU-bound at floor.
// Split-K partials summed during the smem fill.
// ============================================================
#define P_TI 16
#define P_TJ 32
#define P_HC 64
#define P_PAD 66

__global__ __launch_bounds__(256) void k2_pair(const float* __restrict__ W2) {
    __shared__ __align__(16) float as[P_TJ][P_PAD];   // ap rows (j)
    __shared__ __align__(16) float bs[P_TI][P_PAD];   // bp rows (i)
    __shared__ __align__(16) float w2s[2][P_HC];

    const int t = threadIdx.x;
    const int tx = t & 15;   // j
    const int ty = t >> 4;   // i (16 values)
    const int jblk = blockIdx.x * P_TJ;
    const int iblk = blockIdx.y * P_TI;

    ull acc[2][2];
    acc[0][0] = acc[0][1] = acc[1][0] = acc[1][1] = 0ull;

    for (int hb = 0; hb < H; hb += P_HC) {
#pragma unroll
        for (int qq = 0; qq < 4; qq++) {
            int idx = t + qq * 256;
            int rr = idx >> 5, c = (idx & 31) * 2;
            const int gi = (jblk + rr) * H + hb + c;
            *(ull*)&as[rr][c] = fadd2(*(const ull*)&g_ap0[gi],
                                      *(const ull*)&g_ap1[gi]);
        }
#pragma unroll
        for (int qq = 0; qq < 2; qq++) {
            int idx = t + qq * 256;
            int rr = idx >> 5, c = (idx & 31) * 2;
            const int gi = (iblk + rr) * H + hb + c;
            *(ull*)&bs[rr][c] = fadd2(*(const ull*)&g_bp0[gi],
                                      *(const ull*)&g_bp1[gi]);
        }
        if (t < 64) {
            int rr = t >> 5, c = (t & 31) * 2;
            *(float2*)&w2s[rr][c] = *(const float2*)&W2[rr * H + hb + c];
        }
        __syncthreads();

#pragma unroll 16
        for (int hp = 0; hp < P_HC / 2; hp++) {
            ull a0 = *(const ull*)&as[tx][hp * 2];
            ull a1 = *(const ull*)&as[tx + 16][hp * 2];
            ull b0 = *(const ull*)&bs[ty][hp * 2];
            ull w0 = *(const ull*)&w2s[0][hp * 2];
            ull w1 = *(const ull*)&w2s[1][hp * 2];

            ull t0 = tanh2(fadd2(a0, b0));
            ull t1 = tanh2(fadd2(a1, b0));

            acc[0][0] = ffma2(t0, w0, acc[0][0]);
            acc[0][1] = ffma2(t0, w1, acc[0][1]);
            acc[1][0] = ffma2(t1, w0, acc[1][0]);
            acc[1][1] = ffma2(t1, w1, acc[1][1]);
        }
        __syncthreads();
    }

    const int i = iblk + ty;
#pragma unroll
    for (int jv = 0; jv < 2; jv++) {
        const int j = jblk + tx + jv * 16;
        float2 s0 = u2f2(acc[jv][0]);
        float2 s1 = u2f2(acc[jv][1]);
        float2 o;
        o.x = s0.x + s0.y;
        o.y = s1.x + s1.y;
        *(float2*)&g_f[(i * L + j) * 2] = o;
    }
}

// ============================================================
// Kernel 3: out[i,j,c] = 0.5*(f[i,j,c] + f[j,i,c]) + b2[c]
// ============================================================
__global__ __launch_bounds__(256) void k3_sym(const float* __restrict__ b2,
                                              float* __restrict__ out) {
    const int idx = blockIdx.x * 256 + threadIdx.x;
    const int i = idx >> 9;
    const int j = idx & (L - 1);
    const float2 fij = *(const float2*)&g_f[idx * 2];
    const float2 fji = *(const float2*)&g_f[((j << 9) | i) * 2];
    float2 r;
    r.x = (fij.x + fji.x) * 0.5f + b2[0];
    r.y = (fij.y + fji.y) * 0.5f + b2[1];
    *(float2*)&out[idx * 2] = r;
}

extern "C" void kernel_launch(void* const* d_in, const int* in_sizes, int n_in,
                              void* d_out, int out_size) {
    const float* x  = (const float*)d_in[0];
    const float* W1 = (const float*)d_in[1];
    const float* b1 = (const float*)d_in[2];
    const float* W2 = (const float*)d_in[3];
    const float* b2 = (const float*)d_in[4];
    float* out = (float*)d_out;

    cudaFuncSetAttribute(k1_mma, cudaFuncAttributeMaxDynamicSharedMemorySize,
                         K1_SMEM);

    k1_mma<<<dim3(H / 32, L / 64, 2), 128, K1_SMEM>>>(x, W1, b1);
    k2_pair<<<dim3(L / P_TJ, L / P_TI), 256>>>(W2);
    k3_sym<<<(L * L) / 256, 256>>>(b2, out);
}

// round 15
// speedup vs baseline: 1.1766x; 1.1766x over previous
#include <cuda_runtime.h>
#include <cstdint>

typedef unsigned long long ull;
typedef unsigned int u32;

#define L 512
#define H 1024
#define C 2

// Scratch
__device__ float g_ap[L * H];      // a_proj + b1, [l][o]
__device__ float g_bp[L * H];      // b_proj,      [l][o]
__device__ float g_f[L * L * C];   // unsymmetrized logits f[i][j][c]

// ---- packed f32x2 helpers ----
__device__ __forceinline__ ull ffma2(ull a, ull b, ull c) {
    ull d;
    asm("fma.rn.f32x2 %0, %1, %2, %3;" : "=l"(d) : "l"(a), "l"(b), "l"(c));
    return d;
}
__device__ __forceinline__ ull fadd2(ull a, ull b) {
    ull d;
    asm("add.rn.f32x2 %0, %1, %2;" : "=l"(d) : "l"(a), "l"(b));
    return d;
}
__device__ __forceinline__ float2 u2f2(ull u) {
    float2 v;
    asm("mov.b64 {%0, %1}, %2;" : "=f"(v.x), "=f"(v.y) : "l"(u));
    return v;
}
__device__ __forceinline__ ull tanh2(ull x) {
    ull r;
    asm("{\n\t"
        ".reg .f32 lo, hi;\n\t"
        "mov.b64 {lo, hi}, %1;\n\t"
        "tanh.approx.f32 lo, lo;\n\t"
        "tanh.approx.f32 hi, hi;\n\t"
        "mov.b64 %0, {lo, hi};\n\t"
        "}" : "=l"(r) : "l"(x));
    return r;
}
__device__ __forceinline__ u32 smem_u32(const void* p) {
    u32 a;
    asm("{ .reg .u64 tmp; cvta.to.shared.u64 tmp, %1; cvt.u32.u64 %0, tmp; }"
        : "=r"(a) : "l"(p));
    return a;
}
__device__ __forceinline__ void mma_tf32(float c[4], u32 a0, u32 a1, u32 a2, u32 a3,
                                         u32 b0, u32 b1) {
    asm("mma.sync.aligned.m16n8k8.row.col.f32.tf32.tf32.f32 "
        "{%0,%1,%2,%3}, {%4,%5,%6,%7}, {%8,%9}, {%0,%1,%2,%3};"
        : "+f"(c[0]), "+f"(c[1]), "+f"(c[2]), "+f"(c[3])
        : "r"(a0), "r"(a1), "r"(a2), "r"(a3), "r"(b0), "r"(b1));
}
__device__ __forceinline__ void ldsm_x4(u32& r0, u32& r1, u32& r2, u32& r3, u32 addr) {
    asm volatile("ldmatrix.sync.aligned.m8n8.x4.shared.b16 {%0,%1,%2,%3}, [%4];"
                 : "=r"(r0), "=r"(r1), "=r"(r2), "=r"(r3) : "r"(addr));
}
__device__ __forceinline__ void cp16(u32 dst, const void* src) {
    asm volatile("cp.async.ca.shared.global [%0], [%1], 16;"
                 :: "r"(dst), "l"(src) : "memory");
}
#define CP_COMMIT() asm volatile("cp.async.commit_group;" ::: "memory")
#define CP_WAIT1()  asm volatile("cp.async.wait_group 1;" ::: "memory")

// ============================================================
// Kernel 1: tf32 MMA GEMM (R10 exact config, measured 25.4us).
// cp.async 3-stage, ldmatrix, raw-f32-as-tf32 truncation.
// CTA 128 thr, tile 64l x 32o, both ap/bp. Grid (32,8)=256.
// ============================================================
#define B_PAD 36
#define S_WORDS (128 * B_PAD)        // A(64 rows) + WA(32) + WB(32), padded
#define K1_SMEM (3 * S_WORDS * 4)    // 55296 bytes

__global__ __launch_bounds__(128) void k1_mma(const float* __restrict__ x,
                                              const float* __restrict__ W1,
                                              const float* __restrict__ b1) {
    extern __shared__ float sm[];
    const u32 smb = smem_u32(sm);

    const int t = threadIdx.x;
    const int lane = t & 31;
    const int wid = t >> 5;
    const int gid = lane >> 2;
    const int tig = lane & 3;
    const int wm = wid & 1;           // 2 m-warps (32 rows each)
    const int wn = wid >> 1;          // 2 n-warps (16 cols each)
    const int oblk = blockIdx.x * 32;
    const int lblk = blockIdx.y * 64;

    // loader: base row r (0..15), 16B chunk c4; rows r+16q
    const int r = t >> 3;
    const int c4 = (t & 7) * 4;
    const float* xg = x + (lblk + r) * H + c4;
    const float* wg = W1 + (oblk + r) * (2 * H) + c4;

    // ldmatrix per-lane offsets (word units within a stage)
    const int q = lane >> 3, l7 = lane & 7;
    const u32 a_off = (u32)((wm * 32 + ((q & 1) << 3) + l7) * B_PAD + ((q >> 1) << 2));
    const u32 b_off = (u32)((64 + (q >> 1) * 32 + wn * 16 + l7) * B_PAD + ((q & 1) << 2));

    float accA[2][2][4], accB[2][2][4];
#pragma unroll
    for (int mi = 0; mi < 2; mi++)
#pragma unroll
        for (int na = 0; na < 2; na++)
#pragma unroll
            for (int k = 0; k < 4; k++) { accA[mi][na][k] = 0.f; accB[mi][na][k] = 0.f; }

#define PREFETCH(chunk)                                                     \
    do {                                                                    \
        const int kb = (chunk) * 32;                                        \
        const u32 sb = smb + ((chunk) % 3) * S_WORDS * 4;                   \
        _Pragma("unroll")                                                   \
        for (int qq = 0; qq < 4; qq++)                                      \
            cp16(sb + ((r + 16 * qq) * B_PAD + c4) * 4,                     \
                 xg + 16 * qq * H + kb);                                    \
        _Pragma("unroll")                                                   \
        for (int qq = 0; qq < 2; qq++) {                                    \
            cp16(sb + ((64 + r + 16 * qq) * B_PAD + c4) * 4,                \
                 wg + 16 * qq * (2 * H) + kb);                              \
            cp16(sb + ((96 + r + 16 * qq) * B_PAD + c4) * 4,                \
                 wg + 16 * qq * (2 * H) + kb + H);                          \
        }                                                                   \
    } while (0)

#define COMPUTE(stg)                                                        \
    do {                                                                    \
        const u32 abase = smb + (stg) * S_WORDS * 4 + a_off * 4;            \
        const u32 bbase = smb + (stg) * S_WORDS * 4 + b_off * 4;            \
        _Pragma("unroll")                                                   \
        for (int ks = 0; ks < 4; ks++) {                                    \
            u32 A[2][4];                                                    \
            _Pragma("unroll")                                               \
            for (int mi = 0; mi < 2; mi++)                                  \
                ldsm_x4(A[mi][0], A[mi][1], A[mi][2], A[mi][3],             \
                        abase + (mi * 16 * B_PAD + ks * 8) * 4);            \
            _Pragma("unroll")                                               \
            for (int na = 0; na < 2; na++) {                                \
                u32 B0, B1, B2, B3;                                         \
                ldsm_x4(B0, B1, B2, B3,                                     \
                        bbase + (na * 8 * B_PAD + ks * 8) * 4);             \
                _Pragma("unroll")                                           \
                for (int mi = 0; mi < 2; mi++) {                            \
                    mma_tf32(accA[mi][na], A[mi][0], A[mi][1], A[mi][2],    \
                             A[mi][3], B0, B1);                             \
                    mma_tf32(accB[mi][na], A[mi][0], A[mi][1], A[mi][2],    \
                             A[mi][3], B2, B3);                             \
                }                                                           \
            }                                                               \
        }                                                                   \
    } while (0)

    PREFETCH(0); CP_COMMIT();
    PREFETCH(1); CP_COMMIT();

#pragma unroll 1
    for (int it = 0; it < H / 32; it++) {
        CP_WAIT1();
        __syncthreads();
        if (it + 2 < H / 32) PREFETCH(it + 2);
        CP_COMMIT();
        COMPUTE(it % 3);
    }

    // epilogue: c0=(g,2t) c1=(g,2t+1) c2=(g+8,2t) c3=(g+8,2t+1)
#pragma unroll
    for (int mi = 0; mi < 2; mi++) {
        const int row0 = lblk + wm * 32 + mi * 16 + gid;
#pragma unroll
        for (int na = 0; na < 2; na++) {
            const int col = oblk + wn * 16 + na * 8 + tig * 2;
            const float2 bv = *(const float2*)&b1[col];
            float2 v;
            v.x = accA[mi][na][0] + bv.x; v.y = accA[mi][na][1] + bv.y;
            *(float2*)&g_ap[row0 * H + col] = v;
            v.x = accA[mi][na][2] + bv.x; v.y = accA[mi][na][3] + bv.y;
            *(float2*)&g_ap[(row0 + 8) * H + col] = v;
            v.x = accB[mi][na][0]; v.y = accB[mi][na][1];
            *(float2*)&g_bp[row0 * H + col] = v;
            v.x = accB[mi][na][2]; v.y = accB[mi][na][3];
            *(float2*)&g_bp[(row0 + 8) * H + col] = v;
        }
    }
#undef PREFETCH
#undef COMPUTE
}

// ============================================================
// Kernel 2: f[i,j,c] = sum_h tanh(ap[j,h] + bp[i,h]) * W2[c,h]
// Tile 32i x 32j (2i x 2j per thread), 256 threads, HC=64.
// Halves per-output load traffic vs 16x32. MUFU-bound.
// ============================================================
#define P_T 32
#define P_HC 64
#define P_PAD 66

__global__ __launch_bounds__(256) void k2_pair(const float* __restrict__ W2) {
    __shared__ __align__(16) float as[P_T][P_PAD];   // ap rows (j)
    __shared__ __align__(16) float bs[P_T][P_PAD];   // bp rows (i)
    __shared__ __align__(16) float w2s[2][P_HC];

    const int t = threadIdx.x;
    const int tx = t & 15;   // j: tx, tx+16
    const int ty = t >> 4;   // i: ty, ty+16
    const int jblk = blockIdx.x * P_T;
    const int iblk = blockIdx.y * P_T;

    ull acc[2][2][2];   // [iu][jv][c]
#pragma unroll
    for (int a = 0; a < 2; a++)
#pragma unroll
        for (int b = 0; b < 2; b++)
#pragma unroll
            for (int c = 0; c < 2; c++) acc[a][b][c] = 0ull;

    for (int hb = 0; hb < H; hb += P_HC) {
        // as/bs: 32 rows x 64 floats = 1024 float2 each, 4/thread
#pragma unroll
        for (int qq = 0; qq < 4; qq++) {
            int idx = t + qq * 256;
            int rr = idx >> 5, c = (idx & 31) * 2;
            *(float2*)&as[rr][c] = *(const float2*)&g_ap[(jblk + rr) * H + hb + c];
            *(float2*)&bs[rr][c] = *(const float2*)&g_bp[(iblk + rr) * H + hb + c];
        }
        if (t < 64) {
            int rr = t >> 5, c = (t & 31) * 2;
            *(float2*)&w2s[rr][c] = *(const float2*)&W2[rr * H + hb + c];
        }
        __syncthreads();

#pragma unroll 16
        for (int hp = 0; hp < P_HC / 2; hp++) {
            ull a0 = *(const ull*)&as[tx][hp * 2];
            ull a1 = *(const ull*)&as[tx + 16][hp * 2];
            ull b0 = *(const ull*)&bs[ty][hp * 2];
            ull b1v = *(const ull*)&bs[ty + 16][hp * 2];
            ull w0 = *(const ull*)&w2s[0][hp * 2];
            ull w1 = *(const ull*)&w2s[1][hp * 2];

            ull t00 = tanh2(fadd2(a0, b0));
            ull t01 = tanh2(fadd2(a1, b0));
            ull t10 = tanh2(fadd2(a0, b1v));
            ull t11 = tanh2(fadd2(a1, b1v));

            acc[0][0][0] = ffma2(t00, w0, acc[0][0][0]);
            acc[0][0][1] = ffma2(t00, w1, acc[0][0][1]);
            acc[0][1][0] = ffma2(t01, w0, acc[0][1][0]);
            acc[0][1][1] = ffma2(t01, w1, acc[0][1][1]);
            acc[1][0][0] = ffma2(t10, w0, acc[1][0][0]);
            acc[1][0][1] = ffma2(t10, w1, acc[1][0][1]);
            acc[1][1][0] = ffma2(t11, w0, acc[1][1][0]);
            acc[1][1][1] = ffma2(t11, w1, acc[1][1][1]);
        }
        __syncthreads();
    }

#pragma unroll
    for (int iu = 0; iu < 2; iu++) {
        const int i = iblk + ty + iu * 16;
#pragma unroll
        for (int jv = 0; jv < 2; jv++) {
            const int j = jblk + tx + jv * 16;
            float2 s0 = u2f2(acc[iu][jv][0]);
            float2 s1 = u2f2(acc[iu][jv][1]);
            float2 o;
            o.x = s0.x + s0.y;
            o.y = s1.x + s1.y;
            *(float2*)&g_f[(i * L + j) * 2] = o;
        }
    }
}

// ============================================================
// Kernel 3: out[i,j,c] = 0.5*(f[i,j,c] + f[j,i,c]) + b2[c]
// ============================================================
__global__ __launch_bounds__(256) void k3_sym(const float* __restrict__ b2,
                                              float* __restrict__ out) {
    const int idx = blockIdx.x * 256 + threadIdx.x;
    const int i = idx >> 9;
    const int j = idx & (L - 1);
    const float2 fij = *(const float2*)&g_f[idx * 2];
    const float2 fji = *(const float2*)&g_f[((j << 9) | i) * 2];
    float2 r;
    r.x = (fij.x + fji.x) * 0.5f + b2[0];
    r.y = (fij.y + fji.y) * 0.5f + b2[1];
    *(float2*)&out[idx * 2] = r;
}

extern "C" void kernel_launch(void* const* d_in, const int* in_sizes, int n_in,
                              void* d_out, int out_size) {
    const float* x  = (const float*)d_in[0];
    const float* W1 = (const float*)d_in[1];
    const float* b1 = (const float*)d_in[2];
    const float* W2 = (const float*)d_in[3];
    const float* b2 = (const float*)d_in[4];
    float* out = (float*)d_out;

    cudaFuncSetAttribute(k1_mma, cudaFuncAttributeMaxDynamicSharedMemorySize,
                         K1_SMEM);

    k1_mma<<<dim3(H / 32, L / 64), 128, K1_SMEM>>>(x, W1, b1);
    k2_pair<<<dim3(L / P_T, L / P_T), 256>>>(W2);
    k3_sym<<<(L * L) / 256, 256>>>(b2, out);
}

// round 16
// speedup vs baseline: 1.2230x; 1.0394x over previous
#include <cuda_runtime.h>
#include <cstdint>

typedef unsigned long long ull;
typedef unsigned int u32;

#define L 512
#define H 1024
#define C 2

// Scratch
__device__ float g_ap[L * H];      // a_proj + b1, [l][o]
__device__ float g_bp[L * H];      // b_proj,      [l][o]
__device__ float g_f[L * L * C];   // unsymmetrized logits f[i][j][c]

// ---- packed f32x2 helpers ----
__device__ __forceinline__ ull ffma2(ull a, ull b, ull c) {
    ull d;
    asm("fma.rn.f32x2 %0, %1, %2, %3;" : "=l"(d) : "l"(a), "l"(b), "l"(c));
    return d;
}
__device__ __forceinline__ ull fadd2(ull a, ull b) {
    ull d;
    asm("add.rn.f32x2 %0, %1, %2;" : "=l"(d) : "l"(a), "l"(b));
    return d;
}
__device__ __forceinline__ float2 u2f2(ull u) {
    float2 v;
    asm("mov.b64 {%0, %1}, %2;" : "=f"(v.x), "=f"(v.y) : "l"(u));
    return v;
}
__device__ __forceinline__ ull tanh2(ull x) {
    ull r;
    asm("{\n\t"
        ".reg .f32 lo, hi;\n\t"
        "mov.b64 {lo, hi}, %1;\n\t"
        "tanh.approx.f32 lo, lo;\n\t"
        "tanh.approx.f32 hi, hi;\n\t"
        "mov.b64 %0, {lo, hi};\n\t"
        "}" : "=l"(r) : "l"(x));
    return r;
}
__device__ __forceinline__ u32 smem_u32(const void* p) {
    u32 a;
    asm("{ .reg .u64 tmp; cvta.to.shared.u64 tmp, %1; cvt.u32.u64 %0, tmp; }"
        : "=r"(a) : "l"(p));
    return a;
}
__device__ __forceinline__ void mma_tf32(float c[4], u32 a0, u32 a1, u32 a2, u32 a3,
                                         u32 b0, u32 b1) {
    asm("mma.sync.aligned.m16n8k8.row.col.f32.tf32.tf32.f32 "
        "{%0,%1,%2,%3}, {%4,%5,%6,%7}, {%8,%9}, {%0,%1,%2,%3};"
        : "+f"(c[0]), "+f"(c[1]), "+f"(c[2]), "+f"(c[3])
        : "r"(a0), "r"(a1), "r"(a2), "r"(a3), "r"(b0), "r"(b1));
}
__device__ __forceinline__ void ldsm_x4(u32& r0, u32& r1, u32& r2, u32& r3, u32 addr) {
    asm volatile("ldmatrix.sync.aligned.m8n8.x4.shared.b16 {%0,%1,%2,%3}, [%4];"
                 : "=r"(r0), "=r"(r1), "=r"(r2), "=r"(r3) : "r"(addr));
}
__device__ __forceinline__ void cp16(u32 dst, const void* src) {
    asm volatile("cp.async.ca.shared.global [%0], [%1], 16;"
                 :: "r"(dst), "l"(src) : "memory");
}
__device__ __forceinline__ void cp8(u32 dst, const void* src) {
    asm volatile("cp.async.ca.shared.global [%0], [%1], 8;"
                 :: "r"(dst), "l"(src) : "memory");
}
#define CP_COMMIT() asm volatile("cp.async.commit_group;" ::: "memory")
#define CP_WAIT1()  asm volatile("cp.async.wait_group 1;" ::: "memory")

// ============================================================
// Kernel 1: tf32 MMA GEMM (R10/R15 exact config, 24.1us).
// cp.async 3-stage, ldmatrix, raw-f32-as-tf32 truncation.
// CTA 128 thr, tile 64l x 32o, both ap/bp. Grid (32,8)=256.
// ============================================================
#define B_PAD 36
#define S_WORDS (128 * B_PAD)        // A(64 rows) + WA(32) + WB(32), padded
#define K1_SMEM (3 * S_WORDS * 4)    // 55296 bytes

__global__ __launch_bounds__(128) void k1_mma(const float* __restrict__ x,
                                              const float* __restrict__ W1,
                                              const float* __restrict__ b1) {
    extern __shared__ float sm[];
    const u32 smb = smem_u32(sm);

    const int t = threadIdx.x;
    const int lane = t & 31;
    const int wid = t >> 5;
    const int gid = lane >> 2;
    const int tig = lane & 3;
    const int wm = wid & 1;           // 2 m-warps (32 rows each)
    const int wn = wid >> 1;          // 2 n-warps (16 cols each)
    const int oblk = blockIdx.x * 32;
    const int lblk = blockIdx.y * 64;

    // loader: base row r (0..15), 16B chunk c4; rows r+16q
    const int r = t >> 3;
    const int c4 = (t & 7) * 4;
    const float* xg = x + (lblk + r) * H + c4;
    const float* wg = W1 + (oblk + r) * (2 * H) + c4;

    // ldmatrix per-lane offsets (word units within a stage)
    const int q = lane >> 3, l7 = lane & 7;
    const u32 a_off = (u32)((wm * 32 + ((q & 1) << 3) + l7) * B_PAD + ((q >> 1) << 2));
    const u32 b_off = (u32)((64 + (q >> 1) * 32 + wn * 16 + l7) * B_PAD + ((q & 1) << 2));

    float accA[2][2][4], accB[2][2][4];
#pragma unroll
    for (int mi = 0; mi < 2; mi++)
#pragma unroll
        for (int na = 0; na < 2; na++)
#pragma unroll
            for (int k = 0; k < 4; k++) { accA[mi][na][k] = 0.f; accB[mi][na][k] = 0.f; }

#define PREFETCH(chunk)                                                     \
    do {                                                                    \
        const int kb = (chunk) * 32;                                        \
        const u32 sb = smb + ((chunk) % 3) * S_WORDS * 4;                   \
        _Pragma("unroll")                                                   \
        for (int qq = 0; qq < 4; qq++)                                      \
            cp16(sb + ((r + 16 * qq) * B_PAD + c4) * 4,                     \
                 xg + 16 * qq * H + kb);                                    \
        _Pragma("unroll")                                                   \
        for (int qq = 0; qq < 2; qq++) {                                    \
            cp16(sb + ((64 + r + 16 * qq) * B_PAD + c4) * 4,                \
                 wg + 16 * qq * (2 * H) + kb);                              \
            cp16(sb + ((96 + r + 16 * qq) * B_PAD + c4) * 4,                \
                 wg + 16 * qq * (2 * H) + kb + H);                          \
        }                                                                   \
    } while (0)

#define COMPUTE(stg)                                                        \
    do {                                                                    \
        const u32 abase = smb + (stg) * S_WORDS * 4 + a_off * 4;            \
        const u32 bbase = smb + (stg) * S_WORDS * 4 + b_off * 4;            \
        _Pragma("unroll")                                                   \
        for (int ks = 0; ks < 4; ks++) {                                    \
            u32 A[2][4];                                                    \
            _Pragma("unroll")                                               \
            for (int mi = 0; mi < 2; mi++)                                  \
                ldsm_x4(A[mi][0], A[mi][1], A[mi][2], A[mi][3],             \
                        abase + (mi * 16 * B_PAD + ks * 8) * 4);            \
            _Pragma("unroll")                                               \
            for (int na = 0; na < 2; na++) {                                \
                u32 B0, B1, B2, B3;                                         \
                ldsm_x4(B0, B1, B2, B3,                                     \
                        bbase + (na * 8 * B_PAD + ks * 8) * 4);             \
                _Pragma("unroll")                                           \
                for (int mi = 0; mi < 2; mi++) {                            \
                    mma_tf32(accA[mi][na], A[mi][0], A[mi][1], A[mi][2],    \
                             A[mi][3], B0, B1);                             \
                    mma_tf32(accB[mi][na], A[mi][0], A[mi][1], A[mi][2],    \
                             A[mi][3], B2, B3);                             \
                }                                                           \
            }                                                               \
        }                                                                   \
    } while (0)

    PREFETCH(0); CP_COMMIT();
    PREFETCH(1); CP_COMMIT();

#pragma unroll 1
    for (int it = 0; it < H / 32; it++) {
        CP_WAIT1();
        __syncthreads();
        if (it + 2 < H / 32) PREFETCH(it + 2);
        CP_COMMIT();
        COMPUTE(it % 3);
    }

    // epilogue: c0=(g,2t) c1=(g,2t+1) c2=(g+8,2t) c3=(g+8,2t+1)
#pragma unroll
    for (int mi = 0; mi < 2; mi++) {
        const int row0 = lblk + wm * 32 + mi * 16 + gid;
#pragma unroll
        for (int na = 0; na < 2; na++) {
            const int col = oblk + wn * 16 + na * 8 + tig * 2;
            const float2 bv = *(const float2*)&b1[col];
            float2 v;
            v.x = accA[mi][na][0] + bv.x; v.y = accA[mi][na][1] + bv.y;
            *(float2*)&g_ap[row0 * H + col] = v;
            v.x = accA[mi][na][2] + bv.x; v.y = accA[mi][na][3] + bv.y;
            *(float2*)&g_ap[(row0 + 8) * H + col] = v;
            v.x = accB[mi][na][0]; v.y = accB[mi][na][1];
            *(float2*)&g_bp[row0 * H + col] = v;
            v.x = accB[mi][na][2]; v.y = accB[mi][na][3];
            *(float2*)&g_bp[(row0 + 8) * H + col] = v;
        }
    }
#undef PREFETCH
#undef COMPUTE
}

// ============================================================
// Kernel 2: f[i,j,c] = sum_h tanh(ap[j,h] + bp[i,h]) * W2[c,h]
// Tile 32i x 32j (2i x 2j per thread), 256 threads, HC=64,
// 3-stage cp.async ring hides fill latency. MUFU-bound.
// ============================================================
#define P_T 32
#define P_HC 64
#define P_PAD 66
#define P_NB (H / P_HC)              // 16 blocks

__global__ __launch_bounds__(256) void k2_pair(const float* __restrict__ W2) {
    __shared__ __align__(16) float as[3][P_T][P_PAD];   // ap rows (j)
    __shared__ __align__(16) float bs[3][P_T][P_PAD];   // bp rows (i)
    __shared__ __align__(16) float w2s[3][2][P_PAD];

    const int t = threadIdx.x;
    const int tx = t & 15;   // j: tx, tx+16
    const int ty = t >> 4;   // i: ty, ty+16
    const int jblk = blockIdx.x * P_T;
    const int iblk = blockIdx.y * P_T;

    const u32 as_b = smem_u32(as);
    const u32 bs_b = smem_u32(bs);
    const u32 w2_b = smem_u32(w2s);

    ull acc[2][2][2];   // [iu][jv][c]
#pragma unroll
    for (int a = 0; a < 2; a++)
#pragma unroll
        for (int b = 0; b < 2; b++)
#pragma unroll
            for (int c = 0; c < 2; c++) acc[a][b][c] = 0ull;

#define K2_PRE(blk)                                                           \
    do {                                                                      \
        const int hb = (blk) * P_HC;                                          \
        const int s = (blk) % 3;                                              \
        _Pragma("unroll")                                                     \
        for (int qq = 0; qq < 4; qq++) {                                      \
            const int idx = t + qq * 256;                                     \
            const int rr = idx >> 5, cc = (idx & 31) * 2;                     \
            cp8(as_b + ((s * P_T + rr) * P_PAD + cc) * 4,                     \
                &g_ap[(jblk + rr) * H + hb + cc]);                            \
            cp8(bs_b + ((s * P_T + rr) * P_PAD + cc) * 4,                     \
                &g_bp[(iblk + rr) * H + hb + cc]);                            \
        }                                                                     \
        if (t < 64) {                                                         \
            const int rr = t >> 5, cc = (t & 31) * 2;                         \
            cp8(w2_b + ((s * 2 + rr) * P_PAD + cc) * 4,                       \
                &W2[rr * H + hb + cc]);                                       \
        }                                                                     \
    } while (0)

    K2_PRE(0); CP_COMMIT();
    K2_PRE(1); CP_COMMIT();

#pragma unroll 1
    for (int blk = 0; blk < P_NB; blk++) {
        CP_WAIT1();
        __syncthreads();
        if (blk + 2 < P_NB) K2_PRE(blk + 2);
        CP_COMMIT();
        const int s = blk % 3;

#pragma unroll 16
        for (int hp = 0; hp < P_HC / 2; hp++) {
            ull a0 = *(const ull*)&as[s][tx][hp * 2];
            ull a1 = *(const ull*)&as[s][tx + 16][hp * 2];
            ull b0 = *(const ull*)&bs[s][ty][hp * 2];
            ull b1v = *(const ull*)&bs[s][ty + 16][hp * 2];
            ull w0 = *(const ull*)&w2s[s][0][hp * 2];
            ull w1 = *(const ull*)&w2s[s][1][hp * 2];

            ull t00 = tanh2(fadd2(a0, b0));
            ull t01 = tanh2(fadd2(a1, b0));
            ull t10 = tanh2(fadd2(a0, b1v));
            ull t11 = tanh2(fadd2(a1, b1v));

            acc[0][0][0] = ffma2(t00, w0, acc[0][0][0]);
            acc[0][0][1] = ffma2(t00, w1, acc[0][0][1]);
            acc[0][1][0] = ffma2(t01, w0, acc[0][1][0]);
            acc[0][1][1] = ffma2(t01, w1, acc[0][1][1]);
            acc[1][0][0] = ffma2(t10, w0, acc[1][0][0]);
            acc[1][0][1] = ffma2(t10, w1, acc[1][0][1]);
            acc[1][1][0] = ffma2(t11, w0, acc[1][1][0]);
            acc[1][1][1] = ffma2(t11, w1, acc[1][1][1]);
        }
        __syncthreads();
    }

#pragma unroll
    for (int iu = 0; iu < 2; iu++) {
        const int i = iblk + ty + iu * 16;
#pragma unroll
        for (int jv = 0; jv < 2; jv++) {
            const int j = jblk + tx + jv * 16;
            float2 s0 = u2f2(acc[iu][jv][0]);
            float2 s1 = u2f2(acc[iu][jv][1]);
            float2 o;
            o.x = s0.x + s0.y;
            o.y = s1.x + s1.y;
            *(float2*)&g_f[(i * L + j) * 2] = o;
        }
    }
#undef K2_PRE
}

// ============================================================
// Kernel 3: out[i,j,c] = 0.5*(f[i,j,c] + f[j,i,c]) + b2[c]
// ============================================================
__global__ __launch_bounds__(256) void k3_sym(const float* __restrict__ b2,
                                              float* __restrict__ out) {
    const int idx = blockIdx.x * 256 + threadIdx.x;
    const int i = idx >> 9;
    const int j = idx & (L - 1);
    const float2 fij = *(const float2*)&g_f[idx * 2];
    const float2 fji = *(const float2*)&g_f[((j << 9) | i) * 2];
    float2 r;
    r.x = (fij.x + fji.x) * 0.5f + b2[0];
    r.y = (fij.y + fji.y) * 0.5f + b2[1];
    *(float2*)&out[idx * 2] = r;
}

extern "C" void kernel_launch(void* const* d_in, const int* in_sizes, int n_in,
                              void* d_out, int out_size) {
    const float* x  = (const float*)d_in[0];
    const float* W1 = (const float*)d_in[1];
    const float* b1 = (const float*)d_in[2];
    const float* W2 = (const float*)d_in[3];
    const float* b2 = (const float*)d_in[4];
    float* out = (float*)d_out;

    cudaFuncSetAttribute(k1_mma, cudaFuncAttributeMaxDynamicSharedMemorySize,
                         K1_SMEM);

    k1_mma<<<dim3(H / 32, L / 64), 128, K1_SMEM>>>(x, W1, b1);
    k2_pair<<<dim3(L / P_T, L / P_T), 256>>>(W2);
    k3_sym<<<(L * L) / 256, 256>>>(b2, out);
}

// round 17
// speedup vs baseline: 1.3226x; 1.0814x over previous
#include <cuda_runtime.h>
#include <cstdint>

typedef unsigned long long ull;
typedef unsigned int u32;

#define L 512
#define H 1024
#define C 2

// Scratch
__device__ float g_ap[L * H];          // a_proj + b1, [l][o]
__device__ float g_bp[L * H];          // b_proj,      [l][o]
__device__ float g_fp[4][L * L * C];   // per-h-quarter partial logits

// ---- packed f32x2 helpers ----
__device__ __forceinline__ ull ffma2(ull a, ull b, ull c) {
    ull d;
    asm("fma.rn.f32x2 %0, %1, %2, %3;" : "=l"(d) : "l"(a), "l"(b), "l"(c));
    return d;
}
__device__ __forceinline__ ull fadd2(ull a, ull b) {
    ull d;
    asm("add.rn.f32x2 %0, %1, %2;" : "=l"(d) : "l"(a), "l"(b));
    return d;
}
__device__ __forceinline__ float2 u2f2(ull u) {
    float2 v;
    asm("mov.b64 {%0, %1}, %2;" : "=f"(v.x), "=f"(v.y) : "l"(u));
    return v;
}
__device__ __forceinline__ ull tanh2(ull x) {
    ull r;
    asm("{\n\t"
        ".reg .f32 lo, hi;\n\t"
        "mov.b64 {lo, hi}, %1;\n\t"
        "tanh.approx.f32 lo, lo;\n\t"
        "tanh.approx.f32 hi, hi;\n\t"
        "mov.b64 %0, {lo, hi};\n\t"
        "}" : "=l"(r) : "l"(x));
    return r;
}
__device__ __forceinline__ u32 smem_u32(const void* p) {
    u32 a;
    asm("{ .reg .u64 tmp; cvta.to.shared.u64 tmp, %1; cvt.u32.u64 %0, tmp; }"
        : "=r"(a) : "l"(p));
    return a;
}
__device__ __forceinline__ void mma_tf32(float c[4], u32 a0, u32 a1, u32 a2, u32 a3,
                                         u32 b0, u32 b1) {
    asm("mma.sync.aligned.m16n8k8.row.col.f32.tf32.tf32.f32 "
        "{%0,%1,%2,%3}, {%4,%5,%6,%7}, {%8,%9}, {%0,%1,%2,%3};"
        : "+f"(c[0]), "+f"(c[1]), "+f"(c[2]), "+f"(c[3])
        : "r"(a0), "r"(a1), "r"(a2), "r"(a3), "r"(b0), "r"(b1));
}
__device__ __forceinline__ void ldsm_x4(u32& r0, u32& r1, u32& r2, u32& r3, u32 addr) {
    asm volatile("ldmatrix.sync.aligned.m8n8.x4.shared.b16 {%0,%1,%2,%3}, [%4];"
                 : "=r"(r0), "=r"(r1), "=r"(r2), "=r"(r3) : "r"(addr));
}
__device__ __forceinline__ void cp16(u32 dst, const void* src) {
    asm volatile("cp.async.ca.shared.global [%0], [%1], 16;"
                 :: "r"(dst), "l"(src) : "memory");
}
__device__ __forceinline__ void cp8(u32 dst, const void* src) {
    asm volatile("cp.async.ca.shared.global [%0], [%1], 8;"
                 :: "r"(dst), "l"(src) : "memory");
}
#define CP_COMMIT() asm volatile("cp.async.commit_group;" ::: "memory")
#define CP_WAIT1()  asm volatile("cp.async.wait_group 1;" ::: "memory")

// ============================================================
// Kernel 1: tf32 MMA GEMM (R10/R15 exact config, 24.1us).
// cp.async 3-stage, ldmatrix, raw-f32-as-tf32 truncation.
// CTA 128 thr, tile 64l x 32o, both ap/bp. Grid (32,8)=256.
// ============================================================
#define B_PAD 36
#define S_WORDS (128 * B_PAD)        // A(64 rows) + WA(32) + WB(32), padded
#define K1_SMEM (3 * S_WORDS * 4)    // 55296 bytes

__global__ __launch_bounds__(128) void k1_mma(const float* __restrict__ x,
                                              const float* __restrict__ W1,
                                              const float* __restrict__ b1) {
    extern __shared__ float sm[];
    const u32 smb = smem_u32(sm);

    const int t = threadIdx.x;
    const int lane = t & 31;
    const int wid = t >> 5;
    const int gid = lane >> 2;
    const int tig = lane & 3;
    const int wm = wid & 1;           // 2 m-warps (32 rows each)
    const int wn = wid >> 1;          // 2 n-warps (16 cols each)
    const int oblk = blockIdx.x * 32;
    const int lblk = blockIdx.y * 64;

    // loader: base row r (0..15), 16B chunk c4; rows r+16q
    const int r = t >> 3;
    const int c4 = (t & 7) * 4;
    const float* xg = x + (lblk + r) * H + c4;
    const float* wg = W1 + (oblk + r) * (2 * H) + c4;

    // ldmatrix per-lane offsets (word units within a stage)
    const int q = lane >> 3, l7 = lane & 7;
    const u32 a_off = (u32)((wm * 32 + ((q & 1) << 3) + l7) * B_PAD + ((q >> 1) << 2));
    const u32 b_off = (u32)((64 + (q >> 1) * 32 + wn * 16 + l7) * B_PAD + ((q & 1) << 2));

    float accA[2][2][4], accB[2][2][4];
#pragma unroll
    for (int mi = 0; mi < 2; mi++)
#pragma unroll
        for (int na = 0; na < 2; na++)
#pragma unroll
            for (int k = 0; k < 4; k++) { accA[mi][na][k] = 0.f; accB[mi][na][k] = 0.f; }

#define PREFETCH(chunk)                                                     \
    do {                                                                    \
        const int kb = (chunk) * 32;                                        \
        const u32 sb = smb + ((chunk) % 3) * S_WORDS * 4;                   \
        _Pragma("unroll")                                                   \
        for (int qq = 0; qq < 4; qq++)                                      \
            cp16(sb + ((r + 16 * qq) * B_PAD + c4) * 4,                     \
                 xg + 16 * qq * H + kb);                                    \
        _Pragma("unroll")                                                   \
        for (int qq = 0; qq < 2; qq++) {                                    \
            cp16(sb + ((64 + r + 16 * qq) * B_PAD + c4) * 4,                \
                 wg + 16 * qq * (2 * H) + kb);                              \
            cp16(sb + ((96 + r + 16 * qq) * B_PAD + c4) * 4,                \
                 wg + 16 * qq * (2 * H) + kb + H);                          \
        }                                                                   \
    } while (0)

#define COMPUTE(stg)                                                        \
    do {                                                                    \
        const u32 abase = smb + (stg) * S_WORDS * 4 + a_off * 4;            \
        const u32 bbase = smb + (stg) * S_WORDS * 4 + b_off * 4;            \
        _Pragma("unroll")                                                   \
        for (int ks = 0; ks < 4; ks++) {                                    \
            u32 A[2][4];                                                    \
            _Pragma("unroll")                                               \
            for (int mi = 0; mi < 2; mi++)                                  \
                ldsm_x4(A[mi][0], A[mi][1], A[mi][2], A[mi][3],             \
                        abase + (mi * 16 * B_PAD + ks * 8) * 4);            \
            _Pragma("unroll")                                               \
            for (int na = 0; na < 2; na++) {                                \
                u32 B0, B1, B2, B3;                                         \
                ldsm_x4(B0, B1, B2, B3,                                     \
                        bbase + (na * 8 * B_PAD + ks * 8) * 4);             \
                _Pragma("unroll")                                           \
                for (int mi = 0; mi < 2; mi++) {                            \
                    mma_tf32(accA[mi][na], A[mi][0], A[mi][1], A[mi][2],    \
                             A[mi][3], B0, B1);                             \
                    mma_tf32(accB[mi][na], A[mi][0], A[mi][1], A[mi][2],    \
                             A[mi][3], B2, B3);                             \
                }                                                           \
            }                                                               \
        }                                                                   \
    } while (0)

    PREFETCH(0); CP_COMMIT();
    PREFETCH(1); CP_COMMIT();

#pragma unroll 1
    for (int it = 0; it < H / 32; it++) {
        CP_WAIT1();
        __syncthreads();
        if (it + 2 < H / 32) PREFETCH(it + 2);
        CP_COMMIT();
        COMPUTE(it % 3);
    }

    // epilogue: c0=(g,2t) c1=(g,2t+1) c2=(g+8,2t) c3=(g+8,2t+1)
#pragma unroll
    for (int mi = 0; mi < 2; mi++) {
        const int row0 = lblk + wm * 32 + mi * 16 + gid;
#pragma unroll
        for (int na = 0; na < 2; na++) {
            const int col = oblk + wn * 16 + na * 8 + tig * 2;
            const float2 bv = *(const float2*)&b1[col];
            float2 v;
            v.x = accA[mi][na][0] + bv.x; v.y = accA[mi][na][1] + bv.y;
            *(float2*)&g_ap[row0 * H + col] = v;
            v.x = accA[mi][na][2] + bv.x; v.y = accA[mi][na][3] + bv.y;
            *(float2*)&g_ap[(row0 + 8) * H + col] = v;
            v.x = accB[mi][na][0]; v.y = accB[mi][na][1];
            *(float2*)&g_bp[row0 * H + col] = v;
            v.x = accB[mi][na][2]; v.y = accB[mi][na][3];
            *(float2*)&g_bp[(row0 + 8) * H + col] = v;
        }
    }
#undef PREFETCH
#undef COMPUTE
}

// ============================================================
// Kernel 2: partial f over one h-quarter (256 h values).
// Tile 32i x 32j x 256h, grid (16,16,4) = 1024 equal blocks
// -> wave quantization 15% -> 1.2%. 3-stage cp.async ring.
// ============================================================
#define P_T 32
#define P_HC 64
#define P_PAD 66
#define P_HQ (H / 4)                 // 256 h per quarter
#define P_NB (P_HQ / P_HC)           // 4 blocks per quarter

__global__ __launch_bounds__(256) void k2_pair(const float* __restrict__ W2) {
    __shared__ __align__(16) float as[3][P_T][P_PAD];   // ap rows (j)
    __shared__ __align__(16) float bs[3][P_T][P_PAD];   // bp rows (i)
    __shared__ __align__(16) float w2s[3][2][P_PAD];

    const int t = threadIdx.x;
    const int tx = t & 15;   // j: tx, tx+16
    const int ty = t >> 4;   // i: ty, ty+16
    const int jblk = blockIdx.x * P_T;
    const int iblk = blockIdx.y * P_T;
    const int hq = blockIdx.z * P_HQ;
    float* fp = g_fp[blockIdx.z];

    const u32 as_b = smem_u32(as);
    const u32 bs_b = smem_u32(bs);
    const u32 w2_b = smem_u32(w2s);

    ull acc[2][2][2];   // [iu][jv][c]
#pragma unroll
    for (int a = 0; a < 2; a++)
#pragma unroll
        for (int b = 0; b < 2; b++)
#pragma unroll
            for (int c = 0; c < 2; c++) acc[a][b][c] = 0ull;

#define K2_PRE(blk)                                                           \
    do {                                                                      \
        const int hb = hq + (blk) * P_HC;                                     \
        const int s = (blk) % 3;                                              \
        _Pragma("unroll")                                                     \
        for (int qq = 0; qq < 4; qq++) {                                      \
            const int idx = t + qq * 256;                                     \
            const int rr = idx >> 5, cc = (idx & 31) * 2;                     \
            cp8(as_b + ((s * P_T + rr) * P_PAD + cc) * 4,                     \
                &g_ap[(jblk + rr) * H + hb + cc]);                            \
            cp8(bs_b + ((s * P_T + rr) * P_PAD + cc) * 4,                     \
                &g_bp[(iblk + rr) * H + hb + cc]);                            \
        }                                                                     \
        if (t < 64) {                                                         \
            const int rr = t >> 5, cc = (t & 31) * 2;                         \
            cp8(w2_b + ((s * 2 + rr) * P_PAD + cc) * 4,                       \
                &W2[rr * H + hb + cc]);                                       \
        }                                                                     \
    } while (0)

    K2_PRE(0); CP_COMMIT();
    K2_PRE(1); CP_COMMIT();

#pragma unroll 1
    for (int blk = 0; blk < P_NB; blk++) {
        CP_WAIT1();
        __syncthreads();
        if (blk + 2 < P_NB) K2_PRE(blk + 2);
        CP_COMMIT();
        const int s = blk % 3;

#pragma unroll 16
        for (int hp = 0; hp < P_HC / 2; hp++) {
            ull a0 = *(const ull*)&as[s][tx][hp * 2];
            ull a1 = *(const ull*)&as[s][tx + 16][hp * 2];
            ull b0 = *(const ull*)&bs[s][ty][hp * 2];
            ull b1v = *(const ull*)&bs[s][ty + 16][hp * 2];
            ull w0 = *(const ull*)&w2s[s][0][hp * 2];
            ull w1 = *(const ull*)&w2s[s][1][hp * 2];

            ull t00 = tanh2(fadd2(a0, b0));
            ull t01 = tanh2(fadd2(a1, b0));
            ull t10 = tanh2(fadd2(a0, b1v));
            ull t11 = tanh2(fadd2(a1, b1v));

            acc[0][0][0] = ffma2(t00, w0, acc[0][0][0]);
            acc[0][0][1] = ffma2(t00, w1, acc[0][0][1]);
            acc[0][1][0] = ffma2(t01, w0, acc[0][1][0]);
            acc[0][1][1] = ffma2(t01, w1, acc[0][1][1]);
            acc[1][0][0] = ffma2(t10, w0, acc[1][0][0]);
            acc[1][0][1] = ffma2(t10, w1, acc[1][0][1]);
            acc[1][1][0] = ffma2(t11, w0, acc[1][1][0]);
            acc[1][1][1] = ffma2(t11, w1, acc[1][1][1]);
        }
        __syncthreads();
    }

#pragma unroll
    for (int iu = 0; iu < 2; iu++) {
        const int i = iblk + ty + iu * 16;
#pragma unroll
        for (int jv = 0; jv < 2; jv++) {
            const int j = jblk + tx + jv * 16;
            float2 s0 = u2f2(acc[iu][jv][0]);
            float2 s1 = u2f2(acc[iu][jv][1]);
            float2 o;
            o.x = s0.x + s0.y;
            o.y = s1.x + s1.y;
            *(float2*)&fp[(i * L + j) * 2] = o;
        }
    }
#undef K2_PRE
}

// ============================================================
// Kernel 3: out[i,j,c] = 0.5*(sum_z fp[z][i,j,c] + fp[z][j,i,c])
//                        + b2[c]
// ============================================================
__global__ __launch_bounds__(256) void k3_sym(const float* __restrict__ b2,
                                              float* __restrict__ out) {
    const int idx = blockIdx.x * 256 + threadIdx.x;
    const int i = idx >> 9;
    const int j = idx & (L - 1);
    const int tidx = (j << 9) | i;

    ull s = 0ull;
#pragma unroll
    for (int z = 0; z < 4; z++) {
        s = fadd2(s, *(const ull*)&g_fp[z][idx * 2]);
        s = fadd2(s, *(const ull*)&g_fp[z][tidx * 2]);
    }
    float2 sv = u2f2(s);
    float2 r;
    r.x = sv.x * 0.5f + b2[0];
    r.y = sv.y * 0.5f + b2[1];
    *(float2*)&out[idx * 2] = r;
}

extern "C" void kernel_launch(void* const* d_in, const int* in_sizes, int n_in,
                              void* d_out, int out_size) {
    const float* x  = (const float*)d_in[0];
    const float* W1 = (const float*)d_in[1];
    const float* b1 = (const float*)d_in[2];
    const float* W2 = (const float*)d_in[3];
    const float* b2 = (const float*)d_in[4];
    float* out = (float*)d_out;

    cudaFuncSetAttribute(k1_mma, cudaFuncAttributeMaxDynamicSharedMemorySize,
                         K1_SMEM);

    k1_mma<<<dim3(H / 32, L / 64), 128, K1_SMEM>>>(x, W1, b1);
    k2_pair<<<dim3(L / P_T, L / P_T, 4), 256>>>(W2);
    k3_sym<<<(L * L) / 256, 256>>>(b2, out);
}